// round 1
// baseline (speedup 1.0000x reference)
#include <cuda_runtime.h>
#include <cuda_bf16.h>

// Problem constants (fixed by the dataset): B=16, K=64, H=W=96
#define BB   16
#define KK   64
#define HH   96
#define WW   96
#define HW   (HH * WW)          // 9216
#define NPK  (BB * KK)          // 1024 heatmaps per stack
#define NTOT ((size_t)NPK * HW) // 9437184 elems per stack

// Output layout (float32), in reference return order:
//   [0, N)                 Dk
//   [N, 2N)                tf_Dk
//   [2N, 2N+6144)          keypoint   [16, 192, 2]
//   [2N+6144, 2N+12288)    tf_keypoint
//   [2N+12288, +1024)      get_zeta   [16, 64]
//   [2N+13312, +1024)      tf_get_zeta

__device__ __forceinline__ float fast_sigmoid(float x) {
    // 1 / (1 + e^-x) via MUFU.EX2 + MUFU.RCP; rel err ~1e-6 << 1e-3 tolerance
    return __fdividef(1.0f, 1.0f + __expf(-x));
}

__global__ void __launch_bounds__(256)
kp3_kernel(const float* __restrict__ Rk,
           const float* __restrict__ tfRk,
           float* __restrict__ out)
{
    const int stack = blockIdx.x >> 10;     // 0: Rk, 1: tf_Rk
    const int bk    = blockIdx.x & 1023;    // heatmap index within stack
    const int b     = bk >> 6;
    const int k     = bk & 63;

    const float* __restrict__ src = (stack ? tfRk : Rk) + (size_t)bk * HW;
    float* __restrict__ dst = out + (size_t)stack * NTOT + (size_t)bk * HW;

    const int t = threadIdx.x;

    float zeta = 0.f, kx = 0.f, ky = 0.f;

    // 9216 floats = 2304 float4; 256 threads -> 9 vec iterations each.
    // 96 % 4 == 0, so each float4 sits inside one row (same h, w..w+3).
#pragma unroll
    for (int it = 0; it < 9; ++it) {
        const int v   = it * 256 + t;   // float4 index
        const int idx = v << 2;         // element index
        float4 r = reinterpret_cast<const float4*>(src)[v];
        float4 d;
        d.x = fast_sigmoid(r.x);
        d.y = fast_sigmoid(r.y);
        d.z = fast_sigmoid(r.z);
        d.w = fast_sigmoid(r.w);
        reinterpret_cast<float4*>(dst)[v] = d;

        const float h  = (float)(idx / WW);
        const float w0 = (float)(idx - (idx / WW) * WW);
        const float s  = (d.x + d.y) + (d.z + d.w);
        zeta += s;
        ky   += s * h;
        kx   += d.x * w0 + d.y * (w0 + 1.f) + d.z * (w0 + 2.f) + d.w * (w0 + 3.f);
    }

    // ---- block reduction of (zeta, kx, ky) ----
#pragma unroll
    for (int off = 16; off > 0; off >>= 1) {
        zeta += __shfl_down_sync(0xffffffffu, zeta, off);
        kx   += __shfl_down_sync(0xffffffffu, kx,   off);
        ky   += __shfl_down_sync(0xffffffffu, ky,   off);
    }
    __shared__ float sz[8], sx[8], sy[8];
    const int warp = t >> 5, lane = t & 31;
    if (lane == 0) { sz[warp] = zeta; sx[warp] = kx; sy[warp] = ky; }
    __syncthreads();

    if (t == 0) {
        float Z = sz[0], X = sx[0], Y = sy[0];
#pragma unroll
        for (int i = 1; i < 8; ++i) { Z += sz[i]; X += sx[i]; Y += sy[i]; }

        // kp = round(k{x,y} / zeta), round-half-to-even matches jnp.round
        const float kxr = rintf(X / Z);
        const float kyr = rintf(Y / Z);
        const int wx = (int)kxr;
        const int hy = (int)kyr;

        // gather d = Dk[b,k,hy,wx]; recompute with the identical fast-sigmoid
        // formula so it bit-matches the stored Dk value.
        const float d = fast_sigmoid(src[hy * WW + wx]);

        const float kp1x = truncf(kxr + kxr * d);
        const float kp1y = truncf(kyr + kyr * d);
        const float kp2x = truncf(kxr - kxr * d);
        const float kp2y = truncf(kyr - kyr * d);

        float* kp_base = out + 2 * NTOT + (size_t)stack * (BB * 3 * KK * 2);
        // keypoint[b, k, :] / [b, K+k, :] / [b, 2K+k, :]
        const int row = b * (3 * KK);
        kp_base[(row + k)            * 2 + 0] = kxr;
        kp_base[(row + k)            * 2 + 1] = kyr;
        kp_base[(row + KK + k)       * 2 + 0] = kp1x;
        kp_base[(row + KK + k)       * 2 + 1] = kp1y;
        kp_base[(row + 2 * KK + k)   * 2 + 0] = kp2x;
        kp_base[(row + 2 * KK + k)   * 2 + 1] = kp2y;

        float* z_base = out + 2 * NTOT + 2 * (BB * 3 * KK * 2) + (size_t)stack * NPK;
        z_base[bk] = Z;
    }
}

extern "C" void kernel_launch(void* const* d_in, const int* in_sizes, int n_in,
                              void* d_out, int out_size)
{
    const float* Rk   = (const float*)d_in[0];
    const float* tfRk = (const float*)d_in[1];
    float* out = (float*)d_out;
    // 2 stacks * 1024 heatmaps = 2048 CTAs
    kp3_kernel<<<2048, 256>>>(Rk, tfRk, out);
}